// round 1
// baseline (speedup 1.0000x reference)
#include <cuda_runtime.h>

#define BATCH 256
#define NTOK  320
#define CDIM  768
#define LZ    64
#define LK    256
#define SCALE 0.125f

// Scratch: O transposed per batch, [b][c][t] -> flat equals Y[b] (64,768) row-major.
__device__ float g_OT[(size_t)BATCH * CDIM * LZ];

// ---------------- concat-tail copy: out[:,64:,:] = x[:,64:,:] ----------------
__global__ void copy_k(const float4* __restrict__ x4, float4* __restrict__ o4) {
    const int perB  = (LK * CDIM) / 4;      // 49152 float4 per batch
    const int total = BATCH * perB;
    for (int i = blockIdx.x * blockDim.x + threadIdx.x; i < total;
         i += gridDim.x * blockDim.x) {
        int b = i / perB;
        int r = i - b * perB;
        int off = b * (NTOK * CDIM / 4) + (LZ * CDIM / 4) + r;
        o4[off] = x4[off];
    }
}

// ---------------- fused attention per batch ----------------
#define SS_LD  257   // S: 64 x 257 (padded)
#define SK1_LD 33    // pass1 tiles pad
#define SKC_LD 129   // pass2 K-chunk pad (128 cols)
#define STG_LD 68    // OT staging pad (16B aligned rows)
#define POOL_OFF (LZ * SS_LD)

extern __shared__ float smem[];

__global__ __launch_bounds__(256, 1) void attn_k(const float* __restrict__ x) {
    float* sS   = smem;              // 64 x 257 : scores -> probabilities
    float* pool = smem + POOL_OFF;   // reused region

    const int b   = blockIdx.x;
    const int tid = threadIdx.x;
    const int ty  = tid >> 4;        // 0..15
    const int tx  = tid & 15;        // 0..15
    const float* xb = x + (size_t)b * NTOK * CDIM;
    const float* Kb = xb + LZ * CDIM;

    // ---------- Pass 1: S = Q K^T * scale ----------
    float acc[4][16];
#pragma unroll
    for (int i = 0; i < 4; ++i)
#pragma unroll
        for (int j = 0; j < 16; ++j) acc[i][j] = 0.0f;

    float* sQ = pool;                 // 64 x 33
    float* sK = pool + LZ * SK1_LD;   // 256 x 33

    for (int c0 = 0; c0 < CDIM; c0 += 32) {
        // load Q tile 64x32 (coalesced float4)
        {
            int row = tid >> 2, col = (tid & 3) * 8;
            const float4* src = (const float4*)(xb + row * CDIM + c0 + col);
            float4 a = src[0], c = src[1];
            float* d = sQ + row * SK1_LD + col;
            d[0] = a.x; d[1] = a.y; d[2] = a.z; d[3] = a.w;
            d[4] = c.x; d[5] = c.y; d[6] = c.z; d[7] = c.w;
        }
        // load K tile 256x32
#pragma unroll
        for (int p = 0; p < 8; ++p) {
            int row = p * 32 + (tid >> 3), col = (tid & 7) * 4;
            float4 a = *(const float4*)(Kb + row * CDIM + c0 + col);
            float* d = sK + row * SK1_LD + col;
            d[0] = a.x; d[1] = a.y; d[2] = a.z; d[3] = a.w;
        }
        __syncthreads();
#pragma unroll 4
        for (int cc = 0; cc < 32; ++cc) {
            float rQ[4], rK[16];
#pragma unroll
            for (int i = 0; i < 4; ++i) rQ[i] = sQ[(ty * 4 + i) * SK1_LD + cc];
#pragma unroll
            for (int j = 0; j < 16; ++j) rK[j] = sK[(tx + 16 * j) * SK1_LD + cc];
#pragma unroll
            for (int i = 0; i < 4; ++i)
#pragma unroll
                for (int j = 0; j < 16; ++j)
                    acc[i][j] = fmaf(rQ[i], rK[j], acc[i][j]);
        }
        __syncthreads();
    }
#pragma unroll
    for (int i = 0; i < 4; ++i)
#pragma unroll
        for (int j = 0; j < 16; ++j)
            sS[(ty * 4 + i) * SS_LD + tx + 16 * j] = acc[i][j] * SCALE;
    __syncthreads();

    // ---------- softmax over rows (8 warps x 8 rows) ----------
    {
        int w = tid >> 5, lane = tid & 31;
        for (int r = 0; r < 8; ++r) {
            int q = w * 8 + r;
            float* row = sS + q * SS_LD;
            float v[8];
            float mx = -1e30f;
#pragma unroll
            for (int m = 0; m < 8; ++m) {
                v[m] = row[lane + 32 * m];
                mx = fmaxf(mx, v[m]);
            }
#pragma unroll
            for (int s = 16; s > 0; s >>= 1)
                mx = fmaxf(mx, __shfl_xor_sync(0xffffffffu, mx, s));
            float sum = 0.0f;
#pragma unroll
            for (int m = 0; m < 8; ++m) {
                v[m] = expf(v[m] - mx);
                sum += v[m];
            }
#pragma unroll
            for (int s = 16; s > 0; s >>= 1)
                sum += __shfl_xor_sync(0xffffffffu, sum, s);
            float inv = 1.0f / sum;
#pragma unroll
            for (int m = 0; m < 8; ++m) row[lane + 32 * m] = v[m] * inv;
        }
    }
    __syncthreads();

    // ---------- Pass 2: O = P @ K, stored transposed [c][t] ----------
    float* sKc = pool;  // 256 x 129
    for (int c0 = 0; c0 < CDIM; c0 += 128) {
        __syncthreads();  // protect pool reuse (stage reads of prev chunk)
        // load K chunk 256 x 128 (coalesced float4)
#pragma unroll
        for (int p = 0; p < 32; ++p) {
            int idx = p * 256 + tid;
            int row = idx >> 5;
            int colv = (idx & 31) * 4;
            float4 a = *(const float4*)(Kb + row * CDIM + c0 + colv);
            float* d = sKc + row * SKC_LD + colv;
            d[0] = a.x; d[1] = a.y; d[2] = a.z; d[3] = a.w;
        }
        __syncthreads();

        float acc2[4][8];
#pragma unroll
        for (int i = 0; i < 4; ++i)
#pragma unroll
            for (int j = 0; j < 8; ++j) acc2[i][j] = 0.0f;

#pragma unroll 4
        for (int k = 0; k < LK; ++k) {
            float rP[4], rV[8];
#pragma unroll
            for (int i = 0; i < 4; ++i) rP[i] = sS[(ty * 4 + i) * SS_LD + k];
#pragma unroll
            for (int j = 0; j < 8; ++j) rV[j] = sKc[k * SKC_LD + tx + 16 * j];
#pragma unroll
            for (int i = 0; i < 4; ++i)
#pragma unroll
                for (int j = 0; j < 8; ++j)
                    acc2[i][j] = fmaf(rP[i], rV[j], acc2[i][j]);
        }
        __syncthreads();

        // stage transposed [c_local][t]
        float* stage = pool;
#pragma unroll
        for (int i = 0; i < 4; ++i)
#pragma unroll
            for (int j = 0; j < 8; ++j)
                stage[(tx + 16 * j) * STG_LD + ty * 4 + i] = acc2[i][j];
        __syncthreads();

        // coalesced write of 128x64 chunk of O^T
        float* dst = g_OT + (size_t)b * CDIM * LZ + (size_t)c0 * LZ;
#pragma unroll
        for (int p = 0; p < 8; ++p) {
            int idx = p * 1024 + tid * 4;
            int row = idx >> 6;
            int col = idx & 63;
            float4 v = *(float4*)&stage[row * STG_LD + col];
            *(float4*)&dst[row * LZ + col] = v;
        }
    }
}

// ---------------- projection: Z = Y @ W^T + bias, write out[:, :64, :] ----------------
__global__ __launch_bounds__(256, 2) void proj_k(const float* __restrict__ w,
                                                 const float* __restrict__ bias,
                                                 float* __restrict__ out) {
    __shared__ float sY[LZ * 33];     // 64 x 33
    __shared__ float sW[128 * 33];    // 128 x 33

    const int b  = blockIdx.y;
    const int o0 = blockIdx.x * 128;
    const float* Y = g_OT + (size_t)b * CDIM * LZ;  // contiguous (64,768)
    const int tid = threadIdx.x;
    const int ty = tid >> 4, tx = tid & 15;

    float acc[4][8];
#pragma unroll
    for (int i = 0; i < 4; ++i)
#pragma unroll
        for (int j = 0; j < 8; ++j) acc[i][j] = 0.0f;

    for (int k0 = 0; k0 < CDIM; k0 += 32) {
        // Y tile 64x32
        {
            int row = tid >> 2, col = (tid & 3) * 8;
            const float4* src = (const float4*)(Y + row * CDIM + k0 + col);
            float4 a = src[0], c = src[1];
            float* d = sY + row * 33 + col;
            d[0] = a.x; d[1] = a.y; d[2] = a.z; d[3] = a.w;
            d[4] = c.x; d[5] = c.y; d[6] = c.z; d[7] = c.w;
        }
        // W tile 128x32
#pragma unroll
        for (int p = 0; p < 2; ++p) {
            int row = p * 64 + (tid >> 2), col = (tid & 3) * 8;
            const float4* src = (const float4*)(w + (size_t)(o0 + row) * CDIM + k0 + col);
            float4 a = src[0], c = src[1];
            float* d = sW + row * 33 + col;
            d[0] = a.x; d[1] = a.y; d[2] = a.z; d[3] = a.w;
            d[4] = c.x; d[5] = c.y; d[6] = c.z; d[7] = c.w;
        }
        __syncthreads();
#pragma unroll 4
        for (int kk = 0; kk < 32; ++kk) {
            float rY[4], rW[8];
#pragma unroll
            for (int i = 0; i < 4; ++i) rY[i] = sY[(ty * 4 + i) * 33 + kk];
#pragma unroll
            for (int j = 0; j < 8; ++j) rW[j] = sW[(tx + 16 * j) * 33 + kk];
#pragma unroll
            for (int i = 0; i < 4; ++i)
#pragma unroll
                for (int j = 0; j < 8; ++j)
                    acc[i][j] = fmaf(rY[i], rW[j], acc[i][j]);
        }
        __syncthreads();
    }

#pragma unroll
    for (int j = 0; j < 8; ++j) {
        int o = o0 + tx + 16 * j;
        float bv = bias[o];
#pragma unroll
        for (int i = 0; i < 4; ++i) {
            int q = ty * 4 + i;
            out[(size_t)b * NTOK * CDIM + (size_t)q * CDIM + o] = acc[i][j] + bv;
        }
    }
}

extern "C" void kernel_launch(void* const* d_in, const int* in_sizes, int n_in,
                              void* d_out, int out_size) {
    const float* x    = (const float*)d_in[0];
    const float* w    = (const float*)d_in[1];
    const float* bias = (const float*)d_in[2];
    float* out = (float*)d_out;

    // concat tail: out[:,64:,:] = x[:,64:,:]
    copy_k<<<2048, 256>>>((const float4*)x, (float4*)out);

    // fused attention (per-batch CTA)
    size_t smemA = (size_t)(LZ * SS_LD + LK * SKC_LD) * sizeof(float);  // 197888 B
    cudaFuncSetAttribute(attn_k, cudaFuncAttributeMaxDynamicSharedMemorySize, (int)smemA);
    attn_k<<<BATCH, 256, smemA>>>(x);

    // projection + bias into out[:, :64, :]
    proj_k<<<dim3(6, BATCH), 256>>>(w, bias, out);
}

// round 2
// speedup vs baseline: 1.3473x; 1.3473x over previous
#include <cuda_runtime.h>
#include <cstdint>

#define BATCH 256
#define NTOK  320
#define CDIM  768
#define LZ    64
#define LK    256
#define SCALE 0.125f

// Scratch: O transposed per batch, [b][c][t] -> flat equals Y[b] (64,768) row-major.
__device__ float g_OT[(size_t)BATCH * CDIM * LZ];

__device__ __forceinline__ uint32_t f2t(float x) {
    uint32_t r;
    asm("cvt.rna.tf32.f32 %0, %1;" : "=r"(r) : "f"(x));
    return r;
}

__device__ __forceinline__ void mma8(float* d,
                                     uint32_t a0, uint32_t a1, uint32_t a2, uint32_t a3,
                                     uint32_t b0, uint32_t b1) {
    asm volatile(
        "mma.sync.aligned.m16n8k8.row.col.f32.tf32.tf32.f32 "
        "{%0,%1,%2,%3}, {%4,%5,%6,%7}, {%8,%9}, {%0,%1,%2,%3};\n"
        : "+f"(d[0]), "+f"(d[1]), "+f"(d[2]), "+f"(d[3])
        : "r"(a0), "r"(a1), "r"(a2), "r"(a3), "r"(b0), "r"(b1));
}

// ---------------- concat-tail copy: out[:,64:,:] = x[:,64:,:] ----------------
__global__ void copy_k(const float4* __restrict__ x4, float4* __restrict__ o4) {
    const int perB  = (LK * CDIM) / 4;
    const int total = BATCH * perB;
    for (int i = blockIdx.x * blockDim.x + threadIdx.x; i < total;
         i += gridDim.x * blockDim.x) {
        int b = i / perB;
        int r = i - b * perB;
        int off = b * (NTOK * CDIM / 4) + (LZ * CDIM / 4) + r;
        o4[off] = x4[off];
    }
}

// ---------------- fused attention per batch (tf32 tensor cores) ----------------
#define SS_LD  257
#define P1_LD  33
#define K2_LD  65
#define STG_LD 68
#define OFF_POOL (LZ * SS_LD)                    // 16448 words
#define OFF_STG  (OFF_POOL + LK * K2_LD)         // 33088 words
#define SMEM_WORDS (OFF_STG + LZ * STG_LD)       // 37440 words = 149760 B

extern __shared__ float smem[];

__global__ __launch_bounds__(256, 1) void attn_k(const float* __restrict__ x) {
    float*    sS   = smem;                         // 64 x 257 f32 scores -> tf32 probs
    uint32_t* sSu  = (uint32_t*)smem;
    uint32_t* sQu  = (uint32_t*)(smem + OFF_POOL); // 64 x 33 tf32
    uint32_t* sKu  = sQu + LZ * P1_LD;             // 256 x 33 tf32
    uint32_t* sK2  = (uint32_t*)(smem + OFF_POOL); // 256 x 65 tf32 (phase 2)
    float*    stage = smem + OFF_STG;              // 64 x 68 f32

    const int b    = blockIdx.x;
    const int tid  = threadIdx.x;
    const int wid  = tid >> 5;
    const int lane = tid & 31;
    const int grp  = lane >> 2;  // 0..7
    const int qd   = lane & 3;   // 0..3
    const float* xb = x + (size_t)b * NTOK * CDIM;
    const float* Kb = xb + LZ * CDIM;

    // ---------- Phase 1: S = Q K^T * scale (M=64, N=256, red=768) ----------
    const int warp_m = wid >> 2;   // 0..1 -> 32 rows
    const int warp_n = wid & 3;    // 0..3 -> 64 cols

    float acc[2][8][4];
#pragma unroll
    for (int i = 0; i < 2; ++i)
#pragma unroll
        for (int j = 0; j < 8; ++j)
#pragma unroll
            for (int r = 0; r < 4; ++r) acc[i][j][r] = 0.0f;

    for (int c0 = 0; c0 < CDIM; c0 += 32) {
        // Q tile 64x32 -> tf32
        {
            int row = tid >> 2, col = (tid & 3) * 8;
            const float4* src = (const float4*)(xb + row * CDIM + c0 + col);
            float4 a = src[0], c = src[1];
            uint32_t* d = sQu + row * P1_LD + col;
            d[0] = f2t(a.x); d[1] = f2t(a.y); d[2] = f2t(a.z); d[3] = f2t(a.w);
            d[4] = f2t(c.x); d[5] = f2t(c.y); d[6] = f2t(c.z); d[7] = f2t(c.w);
        }
        // K tile 256x32 -> tf32
#pragma unroll
        for (int p = 0; p < 8; ++p) {
            int row = p * 32 + (tid >> 3), col = (tid & 7) * 4;
            float4 a = *(const float4*)(Kb + row * CDIM + c0 + col);
            uint32_t* d = sKu + row * P1_LD + col;
            d[0] = f2t(a.x); d[1] = f2t(a.y); d[2] = f2t(a.z); d[3] = f2t(a.w);
        }
        __syncthreads();

#pragma unroll
        for (int s = 0; s < 4; ++s) {
            int ck = s * 8 + qd;
            uint32_t av[2][4];
#pragma unroll
            for (int mt = 0; mt < 2; ++mt) {
                int rb = warp_m * 32 + mt * 16 + grp;
                av[mt][0] = sQu[rb * P1_LD + ck];
                av[mt][1] = sQu[(rb + 8) * P1_LD + ck];
                av[mt][2] = sQu[rb * P1_LD + ck + 4];
                av[mt][3] = sQu[(rb + 8) * P1_LD + ck + 4];
            }
#pragma unroll
            for (int nt = 0; nt < 8; ++nt) {
                int nb = warp_n * 64 + nt * 8 + grp;
                uint32_t b0 = sKu[nb * P1_LD + ck];
                uint32_t b1 = sKu[nb * P1_LD + ck + 4];
                mma8(acc[0][nt], av[0][0], av[0][1], av[0][2], av[0][3], b0, b1);
                mma8(acc[1][nt], av[1][0], av[1][1], av[1][2], av[1][3], b0, b1);
            }
        }
        __syncthreads();
    }

    // store S (scaled) to smem
#pragma unroll
    for (int mt = 0; mt < 2; ++mt)
#pragma unroll
        for (int nt = 0; nt < 8; ++nt) {
            int r = warp_m * 32 + mt * 16 + grp;
            int c = warp_n * 64 + nt * 8 + 2 * qd;
            sS[r * SS_LD + c]           = acc[mt][nt][0] * SCALE;
            sS[r * SS_LD + c + 1]       = acc[mt][nt][1] * SCALE;
            sS[(r + 8) * SS_LD + c]     = acc[mt][nt][2] * SCALE;
            sS[(r + 8) * SS_LD + c + 1] = acc[mt][nt][3] * SCALE;
        }
    __syncthreads();

    // ---------- softmax (8 warps x 8 rows); final store as tf32 bits ----------
    {
        for (int r = 0; r < 8; ++r) {
            int q = wid * 8 + r;
            float* row = sS + q * SS_LD;
            uint32_t* rowu = sSu + q * SS_LD;
            float v[8];
            float mx = -1e30f;
#pragma unroll
            for (int m = 0; m < 8; ++m) {
                v[m] = row[lane + 32 * m];
                mx = fmaxf(mx, v[m]);
            }
#pragma unroll
            for (int s = 16; s > 0; s >>= 1)
                mx = fmaxf(mx, __shfl_xor_sync(0xffffffffu, mx, s));
            float sum = 0.0f;
#pragma unroll
            for (int m = 0; m < 8; ++m) {
                v[m] = expf(v[m] - mx);
                sum += v[m];
            }
#pragma unroll
            for (int s = 16; s > 0; s >>= 1)
                sum += __shfl_xor_sync(0xffffffffu, sum, s);
            float inv = 1.0f / sum;
#pragma unroll
            for (int m = 0; m < 8; ++m) rowu[lane + 32 * m] = f2t(v[m] * inv);
        }
    }
    __syncthreads();

    // ---------- Phase 2: O = P @ K (M=64, N=64-chunks of c, red=256), store O^T ----------
    const int warp_m2 = wid >> 1;        // 0..3 -> 16 rows
    const int warp_n2 = (wid & 1) * 32;  // 0/32

    for (int c0 = 0; c0 < CDIM; c0 += 64) {
        // load K chunk 256 x 64 -> tf32
#pragma unroll
        for (int p = 0; p < 16; ++p) {
            int idx = p * 256 + tid;
            int row = idx >> 4;
            int colv = (idx & 15) * 4;
            float4 a = *(const float4*)(Kb + row * CDIM + c0 + colv);
            uint32_t* d = sK2 + row * K2_LD + colv;
            d[0] = f2t(a.x); d[1] = f2t(a.y); d[2] = f2t(a.z); d[3] = f2t(a.w);
        }
        __syncthreads();

        float acc2[4][4];
#pragma unroll
        for (int i = 0; i < 4; ++i)
#pragma unroll
            for (int r = 0; r < 4; ++r) acc2[i][r] = 0.0f;

#pragma unroll 4
        for (int ks = 0; ks < 32; ++ks) {
            int kb = ks * 8 + qd;
            int rb = warp_m2 * 16 + grp;
            uint32_t a0 = sSu[rb * SS_LD + kb];
            uint32_t a1 = sSu[(rb + 8) * SS_LD + kb];
            uint32_t a2 = sSu[rb * SS_LD + kb + 4];
            uint32_t a3 = sSu[(rb + 8) * SS_LD + kb + 4];
#pragma unroll
            for (int nt = 0; nt < 4; ++nt) {
                int nb = warp_n2 + nt * 8 + grp;
                uint32_t b0 = sK2[kb * K2_LD + nb];
                uint32_t b1 = sK2[(kb + 4) * K2_LD + nb];
                mma8(acc2[nt], a0, a1, a2, a3, b0, b1);
            }
        }

        // stage transposed [c_local][t]
#pragma unroll
        for (int nt = 0; nt < 4; ++nt) {
            int cc = warp_n2 + nt * 8 + 2 * qd;
            int rq = warp_m2 * 16 + grp;
            stage[cc * STG_LD + rq]           = acc2[nt][0];
            stage[(cc + 1) * STG_LD + rq]     = acc2[nt][1];
            stage[cc * STG_LD + rq + 8]       = acc2[nt][2];
            stage[(cc + 1) * STG_LD + rq + 8] = acc2[nt][3];
        }
        __syncthreads();

        // coalesced write of 64x64 chunk of O^T
        float* dst = g_OT + (size_t)b * CDIM * LZ + (size_t)c0 * LZ;
#pragma unroll
        for (int p = 0; p < 4; ++p) {
            int idx = p * 1024 + tid * 4;
            int row = idx >> 6;
            int col = idx & 63;
            float4 v = *(float4*)&stage[row * STG_LD + col];
            *(float4*)&dst[row * LZ + col] = v;
        }
        __syncthreads();
    }
}

// ---------------- projection: Z = Y @ W^T + bias (tf32 tensor cores) ----------------
__global__ __launch_bounds__(256, 2) void proj_k(const float* __restrict__ w,
                                                 const float* __restrict__ bias,
                                                 float* __restrict__ out) {
    __shared__ uint32_t sY[LZ * 33];     // 64 x 33 tf32
    __shared__ uint32_t sW[128 * 33];    // 128 x 33 tf32

    const int b  = blockIdx.y;
    const int o0 = blockIdx.x * 128;
    const float* Y = g_OT + (size_t)b * CDIM * LZ;  // contiguous (64,768)
    const int tid  = threadIdx.x;
    const int wid  = tid >> 5;
    const int lane = tid & 31;
    const int grp  = lane >> 2;
    const int qd   = lane & 3;
    const int warp_m = wid >> 2;  // 0..1
    const int warp_n = wid & 3;   // 0..3

    float acc[2][4][4];
#pragma unroll
    for (int i = 0; i < 2; ++i)
#pragma unroll
        for (int j = 0; j < 4; ++j)
#pragma unroll
            for (int r = 0; r < 4; ++r) acc[i][j][r] = 0.0f;

    for (int k0 = 0; k0 < CDIM; k0 += 32) {
        // Y tile 64x32
        {
            int row = tid >> 2, col = (tid & 3) * 8;
            const float4* src = (const float4*)(Y + row * CDIM + k0 + col);
            float4 a = src[0], c = src[1];
            uint32_t* d = sY + row * 33 + col;
            d[0] = f2t(a.x); d[1] = f2t(a.y); d[2] = f2t(a.z); d[3] = f2t(a.w);
            d[4] = f2t(c.x); d[5] = f2t(c.y); d[6] = f2t(c.z); d[7] = f2t(c.w);
        }
        // W tile 128x32
#pragma unroll
        for (int p = 0; p < 2; ++p) {
            int row = p * 64 + (tid >> 2), col = (tid & 3) * 8;
            const float4* src = (const float4*)(w + (size_t)(o0 + row) * CDIM + k0 + col);
            float4 a = src[0], c = src[1];
            uint32_t* d = sW + row * 33 + col;
            d[0] = f2t(a.x); d[1] = f2t(a.y); d[2] = f2t(a.z); d[3] = f2t(a.w);
            d[4] = f2t(c.x); d[5] = f2t(c.y); d[6] = f2t(c.z); d[7] = f2t(c.w);
        }
        __syncthreads();

#pragma unroll
        for (int s = 0; s < 4; ++s) {
            int ck = s * 8 + qd;
            uint32_t av[2][4];
#pragma unroll
            for (int mt = 0; mt < 2; ++mt) {
                int rb = warp_m * 32 + mt * 16 + grp;
                av[mt][0] = sY[rb * 33 + ck];
                av[mt][1] = sY[(rb + 8) * 33 + ck];
                av[mt][2] = sY[rb * 33 + ck + 4];
                av[mt][3] = sY[(rb + 8) * 33 + ck + 4];
            }
#pragma unroll
            for (int nt = 0; nt < 4; ++nt) {
                int nb = warp_n * 32 + nt * 8 + grp;
                uint32_t b0 = sW[nb * 33 + ck];
                uint32_t b1 = sW[nb * 33 + ck + 4];
                mma8(acc[0][nt], av[0][0], av[0][1], av[0][2], av[0][3], b0, b1);
                mma8(acc[1][nt], av[1][0], av[1][1], av[1][2], av[1][3], b0, b1);
            }
        }
        __syncthreads();
    }

    // epilogue: bias + store
#pragma unroll
    for (int mt = 0; mt < 2; ++mt)
#pragma unroll
        for (int nt = 0; nt < 4; ++nt) {
            int q = warp_m * 32 + mt * 16 + grp;
            int o = o0 + warp_n * 32 + nt * 8 + 2 * qd;
            float bv0 = bias[o], bv1 = bias[o + 1];
            float2 v0 = make_float2(acc[mt][nt][0] + bv0, acc[mt][nt][1] + bv1);
            float2 v1 = make_float2(acc[mt][nt][2] + bv0, acc[mt][nt][3] + bv1);
            *(float2*)&out[(size_t)b * NTOK * CDIM + (size_t)q * CDIM + o] = v0;
            *(float2*)&out[(size_t)b * NTOK * CDIM + (size_t)(q + 8) * CDIM + o] = v1;
        }
}

extern "C" void kernel_launch(void* const* d_in, const int* in_sizes, int n_in,
                              void* d_out, int out_size) {
    const float* x    = (const float*)d_in[0];
    const float* w    = (const float*)d_in[1];
    const float* bias = (const float*)d_in[2];
    float* out = (float*)d_out;

    copy_k<<<2048, 256>>>((const float4*)x, (float4*)out);

    size_t smemA = (size_t)SMEM_WORDS * sizeof(float);  // 149760 B
    cudaFuncSetAttribute(attn_k, cudaFuncAttributeMaxDynamicSharedMemorySize, (int)smemA);
    attn_k<<<BATCH, 256, smemA>>>(x);

    proj_k<<<dim3(6, BATCH), 256>>>(w, bias, out);
}

// round 3
// speedup vs baseline: 2.6836x; 1.9918x over previous
#include <cuda_runtime.h>
#include <cstdint>

#define BATCH 256
#define NTOK  320
#define CDIM  768
#define LZ    64
#define LK    256
#define SCALE 0.125f

// Scratch: O transposed per batch, [b][c][t] -> flat equals Y[b] (64,768) row-major.
__device__ float g_OT[(size_t)BATCH * CDIM * LZ];

__device__ __forceinline__ uint32_t f2t(float x) {
    uint32_t r;
    asm("cvt.rna.tf32.f32 %0, %1;" : "=r"(r) : "f"(x));
    return r;
}

__device__ __forceinline__ void mma8(float* d,
                                     uint32_t a0, uint32_t a1, uint32_t a2, uint32_t a3,
                                     uint32_t b0, uint32_t b1) {
    asm volatile(
        "mma.sync.aligned.m16n8k8.row.col.f32.tf32.tf32.f32 "
        "{%0,%1,%2,%3}, {%4,%5,%6,%7}, {%8,%9}, {%0,%1,%2,%3};\n"
        : "+f"(d[0]), "+f"(d[1]), "+f"(d[2]), "+f"(d[3])
        : "r"(a0), "r"(a1), "r"(a2), "r"(a3), "r"(b0), "r"(b1));
}

__device__ __forceinline__ void cpa16(uint32_t saddr, const void* gaddr) {
    asm volatile("cp.async.cg.shared.global [%0], [%1], 16;\n"
                 :: "r"(saddr), "l"(gaddr));
}
__device__ __forceinline__ void cpa_commit() {
    asm volatile("cp.async.commit_group;\n");
}
template <int N>
__device__ __forceinline__ void cpa_wait() {
    asm volatile("cp.async.wait_group %0;\n" :: "n"(N));
}

// ---------------- concat-tail copy: out[:,64:,:] = x[:,64:,:] ----------------
__global__ void copy_k(const float4* __restrict__ x4, float4* __restrict__ o4) {
    const int perB  = (LK * CDIM) / 4;
    const int total = BATCH * perB;
    for (int i = blockIdx.x * blockDim.x + threadIdx.x; i < total;
         i += gridDim.x * blockDim.x) {
        int b = i / perB;
        int r = i - b * perB;
        int off = b * (NTOK * CDIM / 4) + (LZ * CDIM / 4) + r;
        o4[off] = x4[off];
    }
}

// ---------------- fused attention per batch (tf32 tensor cores) ----------------
// Conflict-free pads under mma fragment access patterns:
#define P1_LD  36   // 36%32==4 -> bank=4*grp+qd (A/B phase1)
#define SS_LD  260  // 260%32==4 -> A-frag of phase2 conflict-free
#define K2_LD  72   // 72%32==8  -> bank=8*qd+grp (B phase2)
#define STG_LD 68

#define OFF_POOL (LZ * SS_LD)                 // 16640 words
// phase1 pool: Q0,Q1 (64x36 each), K0,K1 (256x36 each) = 23040 words
// phase2 pool: K2 (256x72)=18432, stage (64x68)=4352 = 22784 words
#define SMEM_WORDS (OFF_POOL + 23040)         // 39680 words = 158720 B

extern __shared__ float smem[];

__global__ __launch_bounds__(256, 1) void attn_k(const float* __restrict__ x) {
    float*    sS  = smem;                      // 64 x 260 f32 scores -> tf32 probs
    uint32_t* sSu = (uint32_t*)smem;
    uint32_t* pool = (uint32_t*)(smem + OFF_POOL);
    uint32_t* sQ[2] = { pool, pool + 2304 };
    uint32_t* sK[2] = { pool + 4608, pool + 4608 + 9216 };
    uint32_t* sK2   = pool;                    // phase 2
    float*    stage = (float*)(pool + 18432);  // phase 2

    const int b    = blockIdx.x;
    const int tid  = threadIdx.x;
    const int wid  = tid >> 5;
    const int lane = tid & 31;
    const int grp  = lane >> 2;
    const int qd   = lane & 3;
    const float* xb = x + (size_t)b * NTOK * CDIM;
    const float* Kb = xb + LZ * CDIM;

    const int warp_m = wid >> 2;   // 0..1
    const int warp_n = wid & 3;    // 0..3

    float acc[2][8][4];
#pragma unroll
    for (int i = 0; i < 2; ++i)
#pragma unroll
        for (int j = 0; j < 8; ++j)
#pragma unroll
            for (int r = 0; r < 4; ++r) acc[i][j][r] = 0.0f;

    // cp.async tile loaders (raw f32 bits used as tf32; HW truncates mantissa)
    auto load_tiles = [&](int it, int buf) {
        int c0 = it * 32;
        // Q: 64 rows x 32 cols = 512 16B-chunks, 2 per thread
        {
            uint32_t base = (uint32_t)__cvta_generic_to_shared(sQ[buf]);
#pragma unroll
            for (int p = 0; p < 2; ++p) {
                int id = p * 256 + tid;
                int row = id >> 3, col = (id & 7) * 4;
                cpa16(base + (row * P1_LD + col) * 4, xb + row * CDIM + c0 + col);
            }
        }
        // K: 256 rows x 32 cols = 2048 chunks, 8 per thread
        {
            uint32_t base = (uint32_t)__cvta_generic_to_shared(sK[buf]);
#pragma unroll
            for (int p = 0; p < 8; ++p) {
                int id = p * 256 + tid;
                int row = id >> 3, col = (id & 7) * 4;
                cpa16(base + (row * P1_LD + col) * 4, Kb + row * CDIM + c0 + col);
            }
        }
        cpa_commit();
    };

    // ---------- Phase 1: S = Q K^T * scale, 24 k-tiles of 32, double buffered ----------
    load_tiles(0, 0);
    for (int it = 0; it < 24; ++it) {
        int buf = it & 1;
        if (it + 1 < 24) {
            load_tiles(it + 1, buf ^ 1);
            cpa_wait<1>();
        } else {
            cpa_wait<0>();
        }
        __syncthreads();

        uint32_t* sQu = sQ[buf];
        uint32_t* sKu = sK[buf];
#pragma unroll
        for (int s = 0; s < 4; ++s) {
            int ck = s * 8 + qd;
            uint32_t av[2][4];
#pragma unroll
            for (int mt = 0; mt < 2; ++mt) {
                int rb = warp_m * 32 + mt * 16 + grp;
                av[mt][0] = sQu[rb * P1_LD + ck];
                av[mt][1] = sQu[(rb + 8) * P1_LD + ck];
                av[mt][2] = sQu[rb * P1_LD + ck + 4];
                av[mt][3] = sQu[(rb + 8) * P1_LD + ck + 4];
            }
#pragma unroll
            for (int nt = 0; nt < 8; ++nt) {
                int nb = warp_n * 64 + nt * 8 + grp;
                uint32_t b0 = sKu[nb * P1_LD + ck];
                uint32_t b1 = sKu[nb * P1_LD + ck + 4];
                mma8(acc[0][nt], av[0][0], av[0][1], av[0][2], av[0][3], b0, b1);
                mma8(acc[1][nt], av[1][0], av[1][1], av[1][2], av[1][3], b0, b1);
            }
        }
        __syncthreads();
    }

    // store S (scaled) to smem
#pragma unroll
    for (int mt = 0; mt < 2; ++mt)
#pragma unroll
        for (int nt = 0; nt < 8; ++nt) {
            int r = warp_m * 32 + mt * 16 + grp;
            int c = warp_n * 64 + nt * 8 + 2 * qd;
            sS[r * SS_LD + c]           = acc[mt][nt][0] * SCALE;
            sS[r * SS_LD + c + 1]       = acc[mt][nt][1] * SCALE;
            sS[(r + 8) * SS_LD + c]     = acc[mt][nt][2] * SCALE;
            sS[(r + 8) * SS_LD + c + 1] = acc[mt][nt][3] * SCALE;
        }
    __syncthreads();

    // ---------- softmax (8 warps x 8 rows); store probs as tf32 (RNA) ----------
    for (int r = 0; r < 8; ++r) {
        int q = wid * 8 + r;
        float* row = sS + q * SS_LD;
        uint32_t* rowu = sSu + q * SS_LD;
        float v[8];
        float mx = -1e30f;
#pragma unroll
        for (int m = 0; m < 8; ++m) {
            v[m] = row[lane + 32 * m];
            mx = fmaxf(mx, v[m]);
        }
#pragma unroll
        for (int s = 16; s > 0; s >>= 1)
            mx = fmaxf(mx, __shfl_xor_sync(0xffffffffu, mx, s));
        float sum = 0.0f;
#pragma unroll
        for (int m = 0; m < 8; ++m) {
            v[m] = __expf(v[m] - mx);
            sum += v[m];
        }
#pragma unroll
        for (int s = 16; s > 0; s >>= 1)
            sum += __shfl_xor_sync(0xffffffffu, sum, s);
        float inv = 1.0f / sum;
#pragma unroll
        for (int m = 0; m < 8; ++m) rowu[lane + 32 * m] = f2t(v[m] * inv);
    }
    __syncthreads();

    // ---------- Phase 2: O = P @ K over 12 c-chunks of 64, store O^T ----------
    const int warp_m2 = wid >> 1;        // 0..3
    const int warp_n2 = (wid & 1) * 32;  // 0/32

    for (int c0 = 0; c0 < CDIM; c0 += 64) {
        // load K chunk 256 x 64 (cp.async, single buffer): 4096 chunks, 16/thread
        {
            uint32_t base = (uint32_t)__cvta_generic_to_shared(sK2);
#pragma unroll
            for (int p = 0; p < 16; ++p) {
                int id = p * 256 + tid;
                int row = id >> 4, col = (id & 15) * 4;
                cpa16(base + (row * K2_LD + col) * 4, Kb + row * CDIM + c0 + col);
            }
            cpa_commit();
            cpa_wait<0>();
        }
        __syncthreads();

        float acc2[4][4];
#pragma unroll
        for (int i = 0; i < 4; ++i)
#pragma unroll
            for (int r = 0; r < 4; ++r) acc2[i][r] = 0.0f;

#pragma unroll 4
        for (int ks = 0; ks < 32; ++ks) {
            int kb = ks * 8 + qd;
            int rb = warp_m2 * 16 + grp;
            uint32_t a0 = sSu[rb * SS_LD + kb];
            uint32_t a1 = sSu[(rb + 8) * SS_LD + kb];
            uint32_t a2 = sSu[rb * SS_LD + kb + 4];
            uint32_t a3 = sSu[(rb + 8) * SS_LD + kb + 4];
#pragma unroll
            for (int nt = 0; nt < 4; ++nt) {
                int nb = warp_n2 + nt * 8 + grp;
                uint32_t b0 = sK2[kb * K2_LD + nb];
                uint32_t b1 = sK2[(kb + 4) * K2_LD + nb];
                mma8(acc2[nt], a0, a1, a2, a3, b0, b1);
            }
        }
        __syncthreads();  // sK2 reads done before... (stage is separate; protects next-iter overwrite)

        // stage transposed [c_local][t]
#pragma unroll
        for (int nt = 0; nt < 4; ++nt) {
            int cc = warp_n2 + nt * 8 + 2 * qd;
            int rq = warp_m2 * 16 + grp;
            stage[cc * STG_LD + rq]           = acc2[nt][0];
            stage[(cc + 1) * STG_LD + rq]     = acc2[nt][1];
            stage[cc * STG_LD + rq + 8]       = acc2[nt][2];
            stage[(cc + 1) * STG_LD + rq + 8] = acc2[nt][3];
        }
        __syncthreads();

        // coalesced write of 64x64 chunk of O^T
        float* dst = g_OT + (size_t)b * CDIM * LZ + (size_t)c0 * LZ;
#pragma unroll
        for (int p = 0; p < 4; ++p) {
            int idx = p * 1024 + tid * 4;
            int row = idx >> 6;
            int col = idx & 63;
            float4 v = *(float4*)&stage[row * STG_LD + col];
            *(float4*)&dst[row * LZ + col] = v;
        }
        __syncthreads();
    }
}

// ---------------- projection: Z = Y @ W^T + bias (tf32, cp.async dbuf) ----------------
// dynamic smem: sY[2] 64x36, sW[2] 128x36 -> 13824 words = 55296 B
#define PJ_LD 36
extern __shared__ uint32_t psmem[];

__global__ __launch_bounds__(256, 2) void proj_k(const float* __restrict__ w,
                                                 const float* __restrict__ bias,
                                                 float* __restrict__ out) {
    uint32_t* sY[2] = { psmem, psmem + 2304 };
    uint32_t* sW[2] = { psmem + 4608, psmem + 4608 + 4608 };

    const int b  = blockIdx.y;
    const int o0 = blockIdx.x * 128;
    const float* Y = g_OT + (size_t)b * CDIM * LZ;
    const int tid  = threadIdx.x;
    const int wid  = tid >> 5;
    const int lane = tid & 31;
    const int grp  = lane >> 2;
    const int qd   = lane & 3;
    const int warp_m = wid >> 2;
    const int warp_n = wid & 3;

    float acc[2][4][4];
#pragma unroll
    for (int i = 0; i < 2; ++i)
#pragma unroll
        for (int j = 0; j < 4; ++j)
#pragma unroll
            for (int r = 0; r < 4; ++r) acc[i][j][r] = 0.0f;

    auto load_tiles = [&](int it, int buf) {
        int k0 = it * 32;
        {
            uint32_t base = (uint32_t)__cvta_generic_to_shared(sY[buf]);
#pragma unroll
            for (int p = 0; p < 2; ++p) {
                int id = p * 256 + tid;
                int row = id >> 3, col = (id & 7) * 4;
                cpa16(base + (row * PJ_LD + col) * 4, Y + row * CDIM + k0 + col);
            }
        }
        {
            uint32_t base = (uint32_t)__cvta_generic_to_shared(sW[buf]);
#pragma unroll
            for (int p = 0; p < 4; ++p) {
                int id = p * 256 + tid;
                int row = id >> 3, col = (id & 7) * 4;
                cpa16(base + (row * PJ_LD + col) * 4,
                      w + (size_t)(o0 + row) * CDIM + k0 + col);
            }
        }
        cpa_commit();
    };

    load_tiles(0, 0);
    for (int it = 0; it < 24; ++it) {
        int buf = it & 1;
        if (it + 1 < 24) {
            load_tiles(it + 1, buf ^ 1);
            cpa_wait<1>();
        } else {
            cpa_wait<0>();
        }
        __syncthreads();

        uint32_t* sYu = sY[buf];
        uint32_t* sWu = sW[buf];
#pragma unroll
        for (int s = 0; s < 4; ++s) {
            int ck = s * 8 + qd;
            uint32_t av[2][4];
#pragma unroll
            for (int mt = 0; mt < 2; ++mt) {
                int rb = warp_m * 32 + mt * 16 + grp;
                av[mt][0] = sYu[rb * PJ_LD + ck];
                av[mt][1] = sYu[(rb + 8) * PJ_LD + ck];
                av[mt][2] = sYu[rb * PJ_LD + ck + 4];
                av[mt][3] = sYu[(rb + 8) * PJ_LD + ck + 4];
            }
#pragma unroll
            for (int nt = 0; nt < 4; ++nt) {
                int nb = warp_n * 32 + nt * 8 + grp;
                uint32_t b0 = sWu[nb * PJ_LD + ck];
                uint32_t b1 = sWu[nb * PJ_LD + ck + 4];
                mma8(acc[0][nt], av[0][0], av[0][1], av[0][2], av[0][3], b0, b1);
                mma8(acc[1][nt], av[1][0], av[1][1], av[1][2], av[1][3], b0, b1);
            }
        }
        __syncthreads();
    }

    // epilogue: bias + store
#pragma unroll
    for (int mt = 0; mt < 2; ++mt)
#pragma unroll
        for (int nt = 0; nt < 4; ++nt) {
            int q = warp_m * 32 + mt * 16 + grp;
            int o = o0 + warp_n * 32 + nt * 8 + 2 * qd;
            float bv0 = bias[o], bv1 = bias[o + 1];
            float2 v0 = make_float2(acc[mt][nt][0] + bv0, acc[mt][nt][1] + bv1);
            float2 v1 = make_float2(acc[mt][nt][2] + bv0, acc[mt][nt][3] + bv1);
            *(float2*)&out[(size_t)b * NTOK * CDIM + (size_t)q * CDIM + o] = v0;
            *(float2*)&out[(size_t)b * NTOK * CDIM + (size_t)(q + 8) * CDIM + o] = v1;
        }
}

extern "C" void kernel_launch(void* const* d_in, const int* in_sizes, int n_in,
                              void* d_out, int out_size) {
    const float* x    = (const float*)d_in[0];
    const float* w    = (const float*)d_in[1];
    const float* bias = (const float*)d_in[2];
    float* out = (float*)d_out;

    copy_k<<<2048, 256>>>((const float4*)x, (float4*)out);

    size_t smemA = (size_t)SMEM_WORDS * sizeof(float);  // 158720 B
    cudaFuncSetAttribute(attn_k, cudaFuncAttributeMaxDynamicSharedMemorySize, (int)smemA);
    attn_k<<<BATCH, 256, smemA>>>(x);

    size_t smemP = 13824 * sizeof(uint32_t);  // 55296 B
    cudaFuncSetAttribute(proj_k, cudaFuncAttributeMaxDynamicSharedMemorySize, (int)smemP);
    proj_k<<<dim3(6, BATCH), 256, smemP>>>(w, bias, out);
}